// round 6
// baseline (speedup 1.0000x reference)
#include <cuda_runtime.h>

// QNN_72988674228630: 10-qubit, 2-layer RY+CNOT circuit simulator.
// B = 64 (out_features) * 128 (batch) = 8192 circuits, state = 1024 fp32 amps.
// One warp per circuit: lane holds bits 9..5 of amplitude index, 32 registers
// hold bits 4..0. Qubit q <-> bit position (9-q).
//
// Gate elision: RY(x_q) followed by RY(w_q, layer0) on each qubit before any
// CNOT == RY(x_q + w_q0); the resulting state is a product state constructed
// directly. Remaining work: CNOT chain, layer-2 RYs, CNOT chain, <Z> readout.

static constexpr int N_QUBITS = 10;
static constexpr int N_BATCH  = 128;
static constexpr int OUT_F    = 64;
static constexpr int N_WARPS  = OUT_F * N_BATCH;   // 8192

#define FULL 0xffffffffu

// RY on a lane bit (qubit q = 4 - BIT): cross-lane via shfl.bfly.
// a0' = c*a0 - s*a1 ; a1' = s*a0 + c*a1  -> new = c*mine + (bit? +s : -s)*partner
template <int BIT>
__device__ __forceinline__ void ry_lane(float (&a)[32], float c, float s, int lane) {
    const float ss = ((lane >> BIT) & 1) ? s : -s;
#pragma unroll
    for (int j = 0; j < 32; j++) {
        float p = __shfl_xor_sync(FULL, a[j], 1 << BIT);
        a[j] = fmaf(c, a[j], ss * p);
    }
}

// RY on a local register bit (qubit q = 9 - P): register-pair rotation.
template <int P>
__device__ __forceinline__ void ry_local(float (&a)[32], float c, float s) {
#pragma unroll
    for (int j = 0; j < 32; j++) {
        if (((j >> P) & 1) == 0) {
            const int j1 = j | (1 << P);
            float v0 = a[j], v1 = a[j1];
            a[j]  = fmaf(c, v0, -s * v1);
            a[j1] = fmaf(s, v0,  c * v1);
        }
    }
}

// CNOT with control and target both lane bits (CB > TB, both in 0..4).
template <int CB, int TB>
__device__ __forceinline__ void cnot_lane(float (&a)[32], int lane) {
    const int ctrl = (lane >> CB) & 1;
#pragma unroll
    for (int j = 0; j < 32; j++) {
        float t = __shfl_xor_sync(FULL, a[j], 1 << TB);
        a[j] = ctrl ? t : a[j];
    }
}

// CNOT control = lane bit 0 (position 5), target = local bit 4.
__device__ __forceinline__ void cnot_boundary(float (&a)[32], int lane) {
    const int ctrl = lane & 1;
#pragma unroll
    for (int j = 0; j < 16; j++) {
        float t0 = a[j], t1 = a[j | 16];
        a[j]      = ctrl ? t1 : t0;
        a[j | 16] = ctrl ? t0 : t1;
    }
}

// CNOT with control and target both local bits (PC > PT, both in 0..4):
// pure compile-time register permutation.
template <int PC, int PT>
__device__ __forceinline__ void cnot_local(float (&a)[32]) {
#pragma unroll
    for (int j = 0; j < 32; j++) {
        if ((((j >> PC) & 1) == 1) && (((j >> PT) & 1) == 0)) {
            const int j1 = j ^ (1 << PT);
            float t = a[j]; a[j] = a[j1]; a[j1] = t;
        }
    }
}

// Full CNOT chain q = 0..8: (bit pc, pt) = (9,8),(8,7),...,(1,0).
__device__ __forceinline__ void cnot_chain(float (&a)[32], int lane) {
    cnot_lane<4, 3>(a, lane);   // q=0
    cnot_lane<3, 2>(a, lane);   // q=1
    cnot_lane<2, 1>(a, lane);   // q=2
    cnot_lane<1, 0>(a, lane);   // q=3
    cnot_boundary(a, lane);     // q=4 (lane bit0 -> local bit4)
    cnot_local<4, 3>(a);        // q=5
    cnot_local<3, 2>(a);        // q=6
    cnot_local<2, 1>(a);        // q=7
    cnot_local<1, 0>(a);        // q=8
}

__global__ __launch_bounds__(256)
void qnn_kernel(const float* __restrict__ x,      // [128, 10]
                const float* __restrict__ w,      // [64, 10, 2]
                float* __restrict__ out)          // [64, 128] flat
{
    const int warp = (blockIdx.x * blockDim.x + threadIdx.x) >> 5;
    if (warp >= N_WARPS) return;
    const int lane = threadIdx.x & 31;
    const int of = warp >> 7;          // out_feature
    const int nb = warp & 127;         // batch index

    // Angles: layer-1 merged with data RY (t1 = x + w0), layer-2 separate (t2 = w1).
    float c1[N_QUBITS], s1[N_QUBITS], c2[N_QUBITS], s2[N_QUBITS];
#pragma unroll
    for (int q = 0; q < N_QUBITS; q++) {
        const float t1 = x[nb * N_QUBITS + q] + w[of * (N_QUBITS * 2) + q * 2 + 0];
        const float t2 = w[of * (N_QUBITS * 2) + q * 2 + 1];
        __sincosf(0.5f * t1, &s1[q], &c1[q]);
        __sincosf(0.5f * t2, &s2[q], &c2[q]);
    }

    // Product-state construction of the post-layer-1 state.
    // Amplitude index i = (lane << 5) | j.  Bit position p -> qubit 9-p.
    // Lane bit k (position 5+k) -> qubit 4-k; local bit k -> qubit 9-k.
    float lf = 1.0f;
#pragma unroll
    for (int k = 0; k < 5; k++)
        lf *= ((lane >> k) & 1) ? s1[4 - k] : c1[4 - k];

    float a[32];
#pragma unroll
    for (int j = 0; j < 32; j++) {
        float v = lf;
#pragma unroll
        for (int k = 0; k < 5; k++)
            v *= ((j >> k) & 1) ? s1[9 - k] : c1[9 - k];
        a[j] = v;
    }

    // Layer 1 entangler.
    cnot_chain(a, lane);

    // Layer 2 rotations: qubit q at bit position 9-q.
    ry_lane<4>(a, c2[0], s2[0], lane);
    ry_lane<3>(a, c2[1], s2[1], lane);
    ry_lane<2>(a, c2[2], s2[2], lane);
    ry_lane<1>(a, c2[3], s2[3], lane);
    ry_lane<0>(a, c2[4], s2[4], lane);
    ry_local<4>(a, c2[5], s2[5]);
    ry_local<3>(a, c2[6], s2[6]);
    ry_local<2>(a, c2[7], s2[7]);
    ry_local<1>(a, c2[8], s2[8]);
    ry_local<0>(a, c2[9], s2[9]);

    // Layer 2 entangler.
    cnot_chain(a, lane);

    // Readout: sum_i |a_i|^2 * (10 - 2*popcount(i)).
    const int zl = N_QUBITS - 2 * __popc(lane);
    float sum = 0.0f;
#pragma unroll
    for (int j = 0; j < 32; j++) {
        const float z = (float)(zl - 2 * __popc(j));  // popc(j) folds at compile time
        sum = fmaf(a[j] * a[j], z, sum);
    }
#pragma unroll
    for (int off = 16; off; off >>= 1)
        sum += __shfl_xor_sync(FULL, sum, off);

    if (lane == 0) out[warp] = sum;
}

extern "C" void kernel_launch(void* const* d_in, const int* in_sizes, int n_in,
                              void* d_out, int out_size)
{
    const float* x = (const float*)d_in[0];   // (128, 10) fp32
    const float* w = (const float*)d_in[1];   // (64, 10, 2) fp32
    float* out = (float*)d_out;               // 8192 fp32

    const int threads = 256;                          // 8 warps / block
    const int blocks  = N_WARPS / (threads / 32);     // 1024 blocks
    qnn_kernel<<<blocks, threads>>>(x, w, out);
}

// round 7
// speedup vs baseline: 1.9821x; 1.9821x over previous
#include <cuda_runtime.h>

// QNN_72988674228630: 10-qubit, 2-layer RY+CNOT circuit, 8192 circuits.
// One warp per circuit. Index i (10 bits): lane = bits 9..5, reg j = bits 4..0.
// Qubit q <-> bit position 9-q.
//
// Algebra: chain P is linear over GF(2): M(i)_k = XOR_{m>=k} i_m.
//   psi_f = P R P psi1 = P^2 (P^-1 R P) psi1
// so: chain2 folds into the readout diagonal z(M^2(v)); chain1 conjugates the
// layer-2 RYs into rotations on masks e_k ^ e_{k-1} with suffix-parity
// direction bits. The conjugated layer applied to the product state psi1 is
// evaluated as a cascade: 4 gates on the lane factor (scalar, 4 shfl), then a
// doubling cascade 2->4->8->16->32 absorbing one product factor per gate.

static constexpr int N_WARPS = 8192;   // 64 out_features * 128 batch
#define FULL 0xffffffffu

__global__ __launch_bounds__(256)
void qnn_kernel(const float* __restrict__ x,      // [128, 10]
                const float* __restrict__ w,      // [64, 10, 2]
                float* __restrict__ out)          // [64, 128] flat
{
    const int warp = (blockIdx.x * blockDim.x + threadIdx.x) >> 5;
    if (warp >= N_WARPS) return;
    const int lane = threadIdx.x & 31;
    const int of = warp >> 7;
    const int nb = warp & 127;

    // --- Distributed angles: lane q -> layer1 angle q (x+w0); lane 10+q -> w1.
    float myc = 1.0f, mys = 0.0f;
    {
        float t = 0.0f;
        if (lane < 10)       t = x[nb * 10 + lane] + w[of * 20 + lane * 2];
        else if (lane < 20)  t = w[of * 20 + (lane - 10) * 2 + 1];
        __sincosf(0.5f * t, &mys, &myc);
    }
    float c1[10], s1[10], c2[10], s2[10];
#pragma unroll
    for (int q = 0; q < 10; q++) {
        c1[q] = __shfl_sync(FULL, myc, q);
        s1[q] = __shfl_sync(FULL, mys, q);
        c2[q] = __shfl_sync(FULL, myc, 10 + q);
        s2[q] = __shfl_sync(FULL, mys, 10 + q);
    }

    // --- Lane part of the product state: lane bit b <-> qubit 4-b.
    float lf = 1.0f;
#pragma unroll
    for (int b = 0; b < 5; b++)
        lf *= ((lane >> b) & 1) ? s1[4 - b] : c1[4 - b];

    // --- Conjugated gates q=0..3: act only on the lane factor.
    // masks (lane-bit pairs): 24, 12, 6, 3.  direction bit = suffix parity.
    {
        float ss, p;
        ss = ((lane >> 4) & 1)        ? s2[0] : -s2[0];
        p = __shfl_xor_sync(FULL, lf, 24);
        lf = fmaf(c2[0], lf, ss * p);
        ss = (__popc(lane & 24) & 1) ? s2[1] : -s2[1];
        p = __shfl_xor_sync(FULL, lf, 12);
        lf = fmaf(c2[1], lf, ss * p);
        ss = (__popc(lane & 28) & 1) ? s2[2] : -s2[2];
        p = __shfl_xor_sync(FULL, lf, 6);
        lf = fmaf(c2[2], lf, ss * p);
        ss = (__popc(lane & 30) & 1) ? s2[3] : -s2[3];
        p = __shfl_xor_sync(FULL, lf, 3);
        lf = fmaf(c2[3], lf, ss * p);
    }

    const int par = __popc(lane) & 1;

    // --- q=4 boundary gate: couples lane bit0 with reg bit4. Materializes W1[j4].
    float W1[2];
    {
        float Lp = __shfl_xor_sync(FULL, lf, 1);
        float sp = par ? s2[4] : -s2[4];
        W1[0] = fmaf(c2[4], lf * c1[5], sp * (Lp * s1[5]));
        W1[1] = fmaf(c2[4], lf * s1[5], sp * (Lp * c1[5]));
    }

    // --- q=5: (j4,j3) coupling, absorbs f3 = (c1[6], s1[6]).
    float W2[4];
    {
        float sp = par ? s2[5] : -s2[5];
#pragma unroll
        for (int i = 0; i < 4; i++) {
            const int hi = i >> 1, j3 = i & 1;
            const float f  = j3 ? s1[6] : c1[6];
            const float fb = j3 ? c1[6] : s1[6];
            const float ss = hi ? -sp : sp;          // bit = par ^ j4
            W2[i] = fmaf(c2[5], W1[hi] * f, ss * (W1[hi ^ 1] * fb));
        }
    }

    // --- q=6: (j3,j2) coupling, absorbs f2 = (c1[7], s1[7]).
    float W3[8];
    {
        float sp = par ? s2[6] : -s2[6];
#pragma unroll
        for (int i = 0; i < 8; i++) {
            const int hi = i >> 1, j2 = i & 1;
            const float f  = j2 ? s1[7] : c1[7];
            const float fb = j2 ? c1[7] : s1[7];
            const float ss = (__popc(hi) & 1) ? -sp : sp;  // bit = par ^ j4 ^ j3
            W3[i] = fmaf(c2[6], W2[hi] * f, ss * (W2[hi ^ 1] * fb));
        }
    }

    // --- q=7: (j2,j1) coupling, absorbs f1 = (c1[8], s1[8]).
    float W4[16];
    {
        float sp = par ? s2[7] : -s2[7];
#pragma unroll
        for (int i = 0; i < 16; i++) {
            const int hi = i >> 1, j1 = i & 1;
            const float f  = j1 ? s1[8] : c1[8];
            const float fb = j1 ? c1[8] : s1[8];
            const float ss = (__popc(hi) & 1) ? -sp : sp;
            W4[i] = fmaf(c2[7], W3[hi] * f, ss * (W3[hi ^ 1] * fb));
        }
    }

    // --- q=8: (j1,j0) coupling, absorbs f0 = (c1[9], s1[9]). Full state a[32].
    float a[32];
    {
        float sp = par ? s2[8] : -s2[8];
#pragma unroll
        for (int i = 0; i < 32; i++) {
            const int hi = i >> 1, j0 = i & 1;
            const float f  = j0 ? s1[9] : c1[9];
            const float fb = j0 ? c1[9] : s1[9];
            const float ss = (__popc(hi) & 1) ? -sp : sp;
            a[i] = fmaf(c2[8], W4[hi] * f, ss * (W4[hi ^ 1] * fb));
        }
    }

    // --- q=9: single-bit (j0) coupling, in place. bit = par ^ parity(j).
    {
        float sp = par ? s2[9] : -s2[9];
#pragma unroll
        for (int j = 0; j < 32; j += 2) {
            const float ss = (__popc(j) & 1) ? -sp : sp;
            const float v0 = a[j], v1 = a[j + 1];
            a[j]     = fmaf(c2[9], v0,  ss * v1);
            a[j + 1] = fmaf(c2[9], v1, -ss * v0);
        }
    }

    // --- Readout: out = sum_v |a_v|^2 * z(M^2(v)),  z(i) = 10 - 2*popc(i).
    // M^2 bit k = XOR of bits p>=k with p == k (mod 2).
    // Lane-only bits (k=5..9): A = O + E + (L2^L4) + L3 + L4,
    //   E = L1^L3, O = L0^L2^L4 = par^E.
    // Low bits: g4=j4, g3=j3, g2=j2^j4, g1=j1^j3, g0=j0^j2^j4;
    //   coeff_j = K + ke*ne_j + ko*no_j (ne = g4+g2+g0, no = g3+g1).
    const int E = __popc(lane & 0x0A) & 1;
    const int O = par ^ E;
    const int A = O + E + (((lane >> 2) ^ (lane >> 4)) & 1)
                + ((lane >> 3) & 1) + ((lane >> 4) & 1);
    const float K  = (float)(10 - 2 * A - (E ? 6 : 0) - (O ? 4 : 0));
    const float ke = E ? 2.0f : -2.0f;
    const float ko = O ? 2.0f : -2.0f;

    float sum = 0.0f;
#pragma unroll
    for (int j = 0; j < 32; j++) {
        const int j4 = (j >> 4) & 1, j3 = (j >> 3) & 1, j2 = (j >> 2) & 1;
        const int j1 = (j >> 1) & 1, j0 = j & 1;
        const int ne = j4 + (j2 ^ j4) + (j0 ^ j2 ^ j4);
        const int no = j3 + (j1 ^ j3);
        const float coeff = fmaf(ke, (float)ne, fmaf(ko, (float)no, K));
        sum = fmaf(a[j] * a[j], coeff, sum);
    }
#pragma unroll
    for (int off = 16; off; off >>= 1)
        sum += __shfl_xor_sync(FULL, sum, off);

    if (lane == 0) out[warp] = sum;
}

extern "C" void kernel_launch(void* const* d_in, const int* in_sizes, int n_in,
                              void* d_out, int out_size)
{
    const float* x = (const float*)d_in[0];   // (128, 10) fp32
    const float* w = (const float*)d_in[1];   // (64, 10, 2) fp32
    float* out = (float*)d_out;               // 8192 fp32

    const int threads = 256;                          // 8 warps / block
    const int blocks  = N_WARPS / (threads / 32);     // 1024 blocks
    qnn_kernel<<<blocks, threads>>>(x, w, out);
}

// round 8
// speedup vs baseline: 2.2818x; 1.1512x over previous
#include <cuda_runtime.h>

// QNN_72988674228630: 10-qubit, 2-layer RY+CNOT circuit, 8192 circuits.
// One warp per circuit. Index i (10 bits): lane = bits 9..5, reg j = bits 4..0.
//
// Chain P is GF(2)-linear: psi_f = P R P psi1 = P^2 (P^-1 R P) psi1.
// - chain2 folded into readout diagonal z(M^2(v)) -> 12-entry coeff table.
// - chain1 conjugates layer-2 RYs onto masks e_k^e_{k-1} with suffix-parity
//   signs; applied to the product state psi1 as a doubling cascade.
// - final two cascade gates (q=8: pair coupling, q=9: in-pair rotation) are
//   FUSED: a[2m],a[2m+1] are linear in (W4[m],W4[m^1]) with 8 lane constants
//   A/B/C/D indexed by e=parity(m); squares accumulate directly into sum.

static constexpr int N_WARPS = 8192;   // 64 out_features * 128 batch
#define FULL 0xffffffffu

__device__ constexpr int NEf(int j) {   // #even-position M^2 bits set, from j
    const int j4 = (j >> 4) & 1, j2 = (j >> 2) & 1, j0 = j & 1;
    return j4 + (j2 ^ j4) + (j0 ^ j2 ^ j4);
}
__device__ constexpr int NOf(int j) {   // #odd-position M^2 bits set, from j
    const int j3 = (j >> 3) & 1, j1 = (j >> 1) & 1;
    return j3 + (j1 ^ j3);
}
__device__ constexpr int PARf(int m) {  // compile-time parity
    return (m ^ (m >> 1) ^ (m >> 2) ^ (m >> 3) ^ (m >> 4)) & 1;
}

__global__ __launch_bounds__(256)
void qnn_kernel(const float* __restrict__ x,      // [128, 10]
                const float* __restrict__ w,      // [64, 10, 2]
                float* __restrict__ out)          // [64, 128] flat
{
    __shared__ float angs[8][40];
    const int wib  = threadIdx.x >> 5;
    const int warp = blockIdx.x * 8 + wib;
    const int lane = threadIdx.x & 31;
    const int of = warp >> 7;
    const int nb = warp & 127;

    // --- Angles: lanes 0..9 compute sincos(x_q + w_q0)/2 -> (c1,s1);
    //     lanes 10..19 compute sincos(w_q1)/2 -> (c2,s2). Distribute via smem.
    {
        float t = 0.0f;
        if (lane < 10)      t = x[nb * 10 + lane] + w[of * 20 + lane * 2];
        else if (lane < 20) t = w[of * 20 + (lane - 10) * 2 + 1];
        float s, c;
        __sincosf(0.5f * t, &s, &c);
        if (lane < 10)      { angs[wib][lane]      = c; angs[wib][10 + lane] = s; }
        else if (lane < 20) { angs[wib][10 + lane] = c; angs[wib][20 + lane] = s; }
        __syncwarp();
    }
    float ang[40];
    {
        const float4* ap = (const float4*)angs[wib];
#pragma unroll
        for (int i = 0; i < 10; i++) {
            const float4 v = ap[i];
            ang[4*i+0] = v.x; ang[4*i+1] = v.y; ang[4*i+2] = v.z; ang[4*i+3] = v.w;
        }
    }
#define A_C1(q) ang[(q)]
#define A_S1(q) ang[10 + (q)]
#define A_C2(q) ang[20 + (q)]
#define A_S2(q) ang[30 + (q)]

    // --- Lane-bit suffix parities p_b = XOR of lane bits >= b.
    const int p4  = (lane >> 4) & 1;
    const int p3  = p4 ^ ((lane >> 3) & 1);
    const int p2  = p3 ^ ((lane >> 2) & 1);
    const int p1  = p2 ^ ((lane >> 1) & 1);
    const int par = p1 ^ (lane & 1);

    // --- Lane factor of the product state (lane bit b <-> qubit 4-b).
    float lf;
    lf  = (lane & 1)        ? A_S1(4) : A_C1(4);
    lf *= ((lane >> 1) & 1) ? A_S1(3) : A_C1(3);
    lf *= ((lane >> 2) & 1) ? A_S1(2) : A_C1(2);
    lf *= ((lane >> 3) & 1) ? A_S1(1) : A_C1(1);
    lf *= ((lane >> 4) & 1) ? A_S1(0) : A_C1(0);

    // --- Conjugated gates q=0..3: lane-factor only. Masks 24,12,6,3.
    {
        float ss, p;
        ss = p4 ? A_S2(0) : -A_S2(0);
        p = __shfl_xor_sync(FULL, lf, 24); lf = fmaf(A_C2(0), lf, ss * p);
        ss = p3 ? A_S2(1) : -A_S2(1);
        p = __shfl_xor_sync(FULL, lf, 12); lf = fmaf(A_C2(1), lf, ss * p);
        ss = p2 ? A_S2(2) : -A_S2(2);
        p = __shfl_xor_sync(FULL, lf, 6);  lf = fmaf(A_C2(2), lf, ss * p);
        ss = p1 ? A_S2(3) : -A_S2(3);
        p = __shfl_xor_sync(FULL, lf, 3);  lf = fmaf(A_C2(3), lf, ss * p);
    }

    // --- q=4 boundary gate (lane bit0 x reg bit4): materialize W1[2].
    float W1[2];
    {
        const float Lp = __shfl_xor_sync(FULL, lf, 1);
        const float sp = par ? A_S2(4) : -A_S2(4);
        W1[0] = fmaf(A_C2(4), lf * A_C1(5), sp * (Lp * A_S1(5)));
        W1[1] = fmaf(A_C2(4), lf * A_S1(5), sp * (Lp * A_C1(5)));
    }

    // --- q=5: absorb (c1[6],s1[6]).
    float W2[4];
    {
        const float sp = par ? A_S2(5) : -A_S2(5);
#pragma unroll
        for (int i = 0; i < 4; i++) {
            const int hi = i >> 1, b = i & 1;
            const float f  = b ? A_S1(6) : A_C1(6);
            const float fb = b ? A_C1(6) : A_S1(6);
            const float ss = PARf(hi) ? -sp : sp;
            W2[i] = fmaf(A_C2(5), W1[hi] * f, ss * (W1[hi ^ 1] * fb));
        }
    }

    // --- q=6: absorb (c1[7],s1[7]).
    float W3[8];
    {
        const float sp = par ? A_S2(6) : -A_S2(6);
#pragma unroll
        for (int i = 0; i < 8; i++) {
            const int hi = i >> 1, b = i & 1;
            const float f  = b ? A_S1(7) : A_C1(7);
            const float fb = b ? A_C1(7) : A_S1(7);
            const float ss = PARf(hi) ? -sp : sp;
            W3[i] = fmaf(A_C2(6), W2[hi] * f, ss * (W2[hi ^ 1] * fb));
        }
    }

    // --- q=7: absorb (c1[8],s1[8]).
    float W4[16];
    {
        const float sp = par ? A_S2(7) : -A_S2(7);
#pragma unroll
        for (int i = 0; i < 16; i++) {
            const int hi = i >> 1, b = i & 1;
            const float f  = b ? A_S1(8) : A_C1(8);
            const float fb = b ? A_C1(8) : A_S1(8);
            const float ss = PARf(hi) ? -sp : sp;
            W4[i] = fmaf(A_C2(7), W3[hi] * f, ss * (W3[hi ^ 1] * fb));
        }
    }

    // --- Fused q=8 + q=9 constants. With e = parity(m), sigma8 = (-1)^e sp8,
    // sigma9 = (-1)^e sp9:
    //   a[2m]   = c28*(c29*c9 + s9*sigma9)*W4[m] + sigma8*(c29*s9 + c9*sigma9)*W4[m^1]
    //   a[2m+1] = c28*(c29*s9 - c9*sigma9)*W4[m] + sigma8*(c29*c9 - s9*sigma9)*W4[m^1]
    float Ae[2], Be[2], Ce[2], De[2];
    {
        const float c9 = A_C1(9), s9 = A_S1(9), c29 = A_C2(9), c28 = A_C2(8);
        const float sp9 = par ? A_S2(9) : -A_S2(9);
        const float sp8 = par ? A_S2(8) : -A_S2(8);
        const float P = c29 * c9, Q = c29 * s9;
        const float R = sp9 * s9, Sg = sp9 * c9;
        const float Up = P + R, Um = P - R, Vp = Q + Sg, Vm = Q - Sg;
        Ae[0] = c28 * Up;  Be[0] = sp8 * Vp;   Ce[0] = c28 * Vm;  De[0] = sp8 * Um;
        Ae[1] = c28 * Um;  Be[1] = -sp8 * Vm;  Ce[1] = c28 * Vp;  De[1] = -sp8 * Up;
    }

    // --- Readout coefficient table: coeff = K + ke*ne + ko*no (12 values).
    const int E  = ((lane >> 1) ^ (lane >> 3)) & 1;
    const int O  = par ^ E;
    const int Ab = O + E + (((lane >> 2) ^ (lane >> 4)) & 1)
                 + ((lane >> 3) & 1) + ((lane >> 4) & 1);
    const float K  = (float)(10 - 2 * Ab - (E ? 6 : 0) - (O ? 4 : 0));
    const float ke = E ? 2.0f : -2.0f;
    const float ko = O ? 2.0f : -2.0f;
    float co[12];                         // co[ne*3 + no]
    co[0] = K;          co[3] = K + ke;     co[6] = co[3] + ke;  co[9]  = co[6] + ke;
    co[1] = co[0] + ko; co[4] = co[3] + ko; co[7] = co[6] + ko;  co[10] = co[9] + ko;
    co[2] = co[1] + ko; co[5] = co[4] + ko; co[8] = co[7] + ko;  co[11] = co[10] + ko;

    // --- Fused final gates + square-accumulate readout.
    float sum = 0.0f;
#pragma unroll
    for (int m = 0; m < 16; m++) {
        const int e = PARf(m);
        const float a0 = fmaf(Ae[e], W4[m], Be[e] * W4[m ^ 1]);
        const float a1 = fmaf(Ce[e], W4[m], De[e] * W4[m ^ 1]);
        sum = fmaf(a0 * a0, co[NEf(2 * m) * 3 + NOf(2 * m)], sum);
        sum = fmaf(a1 * a1, co[NEf(2 * m + 1) * 3 + NOf(2 * m + 1)], sum);
    }

#pragma unroll
    for (int off = 16; off; off >>= 1)
        sum += __shfl_xor_sync(FULL, sum, off);

    if (lane == 0) out[warp] = sum;
}

extern "C" void kernel_launch(void* const* d_in, const int* in_sizes, int n_in,
                              void* d_out, int out_size)
{
    const float* x = (const float*)d_in[0];   // (128, 10) fp32
    const float* w = (const float*)d_in[1];   // (64, 10, 2) fp32
    float* out = (float*)d_out;               // 8192 fp32

    const int threads = 256;                       // 8 warps / block
    const int blocks  = N_WARPS / (threads / 32);  // 1024 blocks
    qnn_kernel<<<blocks, threads>>>(x, w, out);
}

// round 9
// speedup vs baseline: 2.4412x; 1.0699x over previous
#include <cuda_runtime.h>

// QNN_72988674228630: 10-qubit, 2-layer RY+CNOT circuit, 8192 circuits.
// One warp simulates TWO circuits (out_features 2h, 2h+1; same batch row) for
// ILP — the per-circuit dependency chains (product -> 4 dependent shfl-rotations
// -> 5-stage doubling cascade) interleave to fill issue slots.
//
// Index i (10 bits): lane = bits 9..5, reg j = bits 4..0.
// Chain P is GF(2)-linear: psi_f = P R P psi1 = P^2 (P^-1 R P) psi1.
// - chain2 folded into the readout diagonal z(M^2(v)) -> 12-entry coeff table
//   (lane-only -> shared by both circuits).
// - chain1 conjugates layer-2 RYs onto masks e_k^e_{k-1} with suffix-parity
//   signs; applied to the product state psi1 as a doubling cascade.
// - final two cascade gates (q=8 pair coupling, q=9 in-pair rotation) fused
//   into one linear map with 8 lane constants; squares accumulate directly.
// Angles live in SMEM and are read at use sites (broadcast LDS) — no 40-float
// local array to spill.

#define FULL 0xffffffffu

__device__ constexpr int NEf(int j) {   // #even-position M^2 bits set, from j
    const int j4 = (j >> 4) & 1, j2 = (j >> 2) & 1, j0 = j & 1;
    return j4 + (j2 ^ j4) + (j0 ^ j2 ^ j4);
}
__device__ constexpr int NOf(int j) {   // #odd-position M^2 bits set, from j
    const int j3 = (j >> 3) & 1, j1 = (j >> 1) & 1;
    return j3 + (j1 ^ j3);
}
__device__ constexpr int PARf(int m) {  // compile-time parity
    return (m ^ (m >> 1) ^ (m >> 2) ^ (m >> 3) ^ (m >> 4)) & 1;
}

// Angle layout per circuit (40 floats): [q]=c1, [10+q]=s1, [20+q]=c2, [30+q]=s2.

__global__ __launch_bounds__(128, 7)
void qnn_kernel(const float* __restrict__ x,      // [128, 10]
                const float* __restrict__ w,      // [64, 10, 2]
                float* __restrict__ out)          // [64, 128] flat
{
    __shared__ float angs[4][2][40];
    const int wib  = threadIdx.x >> 5;
    const int hw   = blockIdx.x * 4 + wib;        // 0..4095 (warp = 2 circuits)
    const int lane = threadIdx.x & 31;
    const int nb  = hw & 127;
    const int ofh = hw >> 7;                      // 0..31

    // --- Angle computation, distributed over lanes, both circuits.
    // Circuit 0 (of=2*ofh): lanes 0..19, q=lane. Circuit 1: lanes 12..31, q=lane-12.
    {
        if (lane < 20) {
            const int q = lane, of = 2 * ofh;
            const float t = (q < 10) ? x[nb * 10 + q] + w[of * 20 + q * 2]
                                     : w[of * 20 + (q - 10) * 2 + 1];
            float s, c; __sincosf(0.5f * t, &s, &c);
            const int base = (q < 10) ? q : (10 + q);
            angs[wib][0][base] = c; angs[wib][0][base + 10] = s;
        }
        if (lane >= 12) {
            const int q = lane - 12, of = 2 * ofh + 1;
            const float t = (q < 10) ? x[nb * 10 + q] + w[of * 20 + q * 2]
                                     : w[of * 20 + (q - 10) * 2 + 1];
            float s, c; __sincosf(0.5f * t, &s, &c);
            const int base = (q < 10) ? q : (10 + q);
            angs[wib][1][base] = c; angs[wib][1][base + 10] = s;
        }
        __syncwarp();
    }
    const float* const Ac[2] = { angs[wib][0], angs[wib][1] };

    // --- Lane-bit suffix parities (shared by both circuits).
    const int p4  = (lane >> 4) & 1;
    const int p3  = p4 ^ ((lane >> 3) & 1);
    const int p2  = p3 ^ ((lane >> 2) & 1);
    const int p1  = p2 ^ ((lane >> 1) & 1);
    const int par = p1 ^ (lane & 1);

    // --- Lane factor of the product state (lane bit b <-> qubit 4-b).
    float lf[2];
#pragma unroll
    for (int c = 0; c < 2; c++) {
        const float* A = Ac[c];
        const float f0 = (lane & 1)        ? A[14] : A[4];
        const float f1 = ((lane >> 1) & 1) ? A[13] : A[3];
        const float f2 = ((lane >> 2) & 1) ? A[12] : A[2];
        const float f3 = ((lane >> 3) & 1) ? A[11] : A[1];
        const float f4 = ((lane >> 4) & 1) ? A[10] : A[0];
        lf[c] = (f0 * f1) * (f2 * f3) * f4;      // shallow tree
    }

    // --- Conjugated gates q=0..3: lane-factor only. Masks 24,12,6,3.
#pragma unroll
    for (int c = 0; c < 2; c++) {
        const float* A = Ac[c];
        float ss, p, v = lf[c];
        ss = p4 ? A[30] : -A[30];
        p = __shfl_xor_sync(FULL, v, 24); v = fmaf(A[20], v, ss * p);
        ss = p3 ? A[31] : -A[31];
        p = __shfl_xor_sync(FULL, v, 12); v = fmaf(A[21], v, ss * p);
        ss = p2 ? A[32] : -A[32];
        p = __shfl_xor_sync(FULL, v, 6);  v = fmaf(A[22], v, ss * p);
        ss = p1 ? A[33] : -A[33];
        p = __shfl_xor_sync(FULL, v, 3);  v = fmaf(A[23], v, ss * p);
        lf[c] = v;
    }

    // --- q=4 boundary gate (lane bit0 x reg bit4): materialize W1.
    float W1[2][2];
#pragma unroll
    for (int c = 0; c < 2; c++) {
        const float* A = Ac[c];
        const float Lp = __shfl_xor_sync(FULL, lf[c], 1);
        const float sp = par ? A[34] : -A[34];
        W1[c][0] = fmaf(A[24], lf[c] * A[5],  sp * (Lp * A[15]));
        W1[c][1] = fmaf(A[24], lf[c] * A[15], sp * (Lp * A[5]));
    }

    // --- q=5: absorb (c1[6], s1[6]).
    float W2[2][4];
#pragma unroll
    for (int c = 0; c < 2; c++) {
        const float* A = Ac[c];
        const float sp = par ? A[35] : -A[35];
#pragma unroll
        for (int i = 0; i < 4; i++) {
            const int hi = i >> 1, b = i & 1;
            const float f  = b ? A[16] : A[6];
            const float fb = b ? A[6]  : A[16];
            const float ss = PARf(hi) ? -sp : sp;
            W2[c][i] = fmaf(A[25], W1[c][hi] * f, ss * (W1[c][hi ^ 1] * fb));
        }
    }

    // --- q=6: absorb (c1[7], s1[7]).
    float W3[2][8];
#pragma unroll
    for (int c = 0; c < 2; c++) {
        const float* A = Ac[c];
        const float sp = par ? A[36] : -A[36];
#pragma unroll
        for (int i = 0; i < 8; i++) {
            const int hi = i >> 1, b = i & 1;
            const float f  = b ? A[17] : A[7];
            const float fb = b ? A[7]  : A[17];
            const float ss = PARf(hi) ? -sp : sp;
            W3[c][i] = fmaf(A[26], W2[c][hi] * f, ss * (W2[c][hi ^ 1] * fb));
        }
    }

    // --- q=7: absorb (c1[8], s1[8]).
    float W4[2][16];
#pragma unroll
    for (int c = 0; c < 2; c++) {
        const float* A = Ac[c];
        const float sp = par ? A[37] : -A[37];
#pragma unroll
        for (int i = 0; i < 16; i++) {
            const int hi = i >> 1, b = i & 1;
            const float f  = b ? A[18] : A[8];
            const float fb = b ? A[8]  : A[18];
            const float ss = PARf(hi) ? -sp : sp;
            W4[c][i] = fmaf(A[27], W3[c][hi] * f, ss * (W3[c][hi ^ 1] * fb));
        }
    }

    // --- Readout coefficient table (lane-only -> shared by both circuits).
    const int E  = ((lane >> 1) ^ (lane >> 3)) & 1;
    const int O  = par ^ E;
    const int Ab = O + E + (((lane >> 2) ^ (lane >> 4)) & 1)
                 + ((lane >> 3) & 1) + ((lane >> 4) & 1);
    const float K  = (float)(10 - 2 * Ab - (E ? 6 : 0) - (O ? 4 : 0));
    const float ke = E ? 2.0f : -2.0f;
    const float ko = O ? 2.0f : -2.0f;
    float co[12];                         // co[ne*3 + no]
    co[0] = K;          co[3] = K + ke;     co[6] = co[3] + ke;  co[9]  = co[6] + ke;
    co[1] = co[0] + ko; co[4] = co[3] + ko; co[7] = co[6] + ko;  co[10] = co[9] + ko;
    co[2] = co[1] + ko; co[5] = co[4] + ko; co[8] = co[7] + ko;  co[11] = co[10] + ko;

    // --- Fused q=8+q=9 + square-accumulate readout, per circuit (frees W4[c]).
    float sum[2];
#pragma unroll
    for (int c = 0; c < 2; c++) {
        const float* A = Ac[c];
        const float c9 = A[9], s9 = A[19], c29 = A[29], c28 = A[28];
        const float sp9 = par ? A[39] : -A[39];
        const float sp8 = par ? A[38] : -A[38];
        const float P = c29 * c9, Q = c29 * s9;
        const float R = sp9 * s9, Sg = sp9 * c9;
        const float Up = P + R, Um = P - R, Vp = Q + Sg, Vm = Q - Sg;
        float Ae[2], Be[2], Ce[2], De[2];
        Ae[0] = c28 * Up;  Be[0] = sp8 * Vp;   Ce[0] = c28 * Vm;  De[0] = sp8 * Um;
        Ae[1] = c28 * Um;  Be[1] = -sp8 * Vm;  Ce[1] = c28 * Vp;  De[1] = -sp8 * Up;

        float s = 0.0f;
#pragma unroll
        for (int m = 0; m < 16; m++) {
            const int e = PARf(m);
            const float a0 = fmaf(Ae[e], W4[c][m], Be[e] * W4[c][m ^ 1]);
            const float a1 = fmaf(Ce[e], W4[c][m], De[e] * W4[c][m ^ 1]);
            s = fmaf(a0 * a0, co[NEf(2 * m) * 3 + NOf(2 * m)], s);
            s = fmaf(a1 * a1, co[NEf(2 * m + 1) * 3 + NOf(2 * m + 1)], s);
        }
        sum[c] = s;
    }

    // --- Warp reductions (interleaved pair of butterflies).
#pragma unroll
    for (int off = 16; off; off >>= 1) {
        sum[0] += __shfl_xor_sync(FULL, sum[0], off);
        sum[1] += __shfl_xor_sync(FULL, sum[1], off);
    }

    if (lane == 0) {
        out[(2 * ofh)     * 128 + nb] = sum[0];
        out[(2 * ofh + 1) * 128 + nb] = sum[1];
    }
}

extern "C" void kernel_launch(void* const* d_in, const int* in_sizes, int n_in,
                              void* d_out, int out_size)
{
    const float* x = (const float*)d_in[0];   // (128, 10) fp32
    const float* w = (const float*)d_in[1];   // (64, 10, 2) fp32
    float* out = (float*)d_out;               // 8192 fp32

    // 4096 warps (2 circuits each), 4 warps/block -> 1024 blocks, one wave.
    qnn_kernel<<<1024, 128>>>(x, w, out);
}

// round 10
// speedup vs baseline: 2.4502x; 1.0037x over previous
#include <cuda_runtime.h>

// QNN_72988674228630: 10-qubit, 2-layer RY+CNOT circuit, 8192 circuits.
// One warp = TWO circuits (out_features 2h,2h+1; same batch row) for ILP.
// Index i (10 bits): lane = bits 9..5, reg j = bits 4..0.
//
// Chain P is GF(2)-linear: psi_f = P R P psi1 = P^2 (P^-1 R P) psi1.
// - chain2 folded into readout diagonal -> 12-entry coeff table (lane-only,
//   shared by both circuits).
// - chain1 conjugates layer-2 RYs onto masks e_k^e_{k-1}; applied to the
//   product state as a doubling cascade.
// - R10: stages q=6..q=9 + readout FUSED into one loop over W2 pairs
//   (group closure: amps 8g..8g+7 depend only on W2[g],W2[g^1]); W3/W4 arrays
//   never materialize -> register live set collapses, occupancy recovers.
//   Each cascade step is 1 FMUL + 1 FFMA via hoisted angle products with
//   compile-time sign folding.

#define FULL 0xffffffffu

__device__ constexpr int NEf(int j) {   // #even-position M^2 bits set, from j
    const int j4 = (j >> 4) & 1, j2 = (j >> 2) & 1, j0 = j & 1;
    return j4 + (j2 ^ j4) + (j0 ^ j2 ^ j4);
}
__device__ constexpr int NOf(int j) {   // #odd-position M^2 bits set, from j
    const int j3 = (j >> 3) & 1, j1 = (j >> 1) & 1;
    return j3 + (j1 ^ j3);
}
__device__ constexpr int PARf(int m) {
    return (m ^ (m >> 1) ^ (m >> 2) ^ (m >> 3) ^ (m >> 4)) & 1;
}

// Angle layout per circuit (40 floats): [q]=c1, [10+q]=s1, [20+q]=c2, [30+q]=s2.

__global__ __launch_bounds__(128, 8)
void qnn_kernel(const float* __restrict__ x,      // [128, 10]
                const float* __restrict__ w,      // [64, 10, 2]
                float* __restrict__ out)          // [64, 128] flat
{
    __shared__ float angs[4][2][40];
    const int wib  = threadIdx.x >> 5;
    const int hw   = blockIdx.x * 4 + wib;        // warp id = 2 circuits
    const int lane = threadIdx.x & 31;
    const int nb  = hw & 127;
    const int ofh = hw >> 7;                      // 0..31

    // --- Angles distributed across lanes (circuit 0: lanes 0..19, circuit 1:
    //     lanes 12..31), written to smem, read back as broadcast LDS.
    if (lane < 20) {
        const int q = lane, of = 2 * ofh;
        const float t = (q < 10) ? x[nb * 10 + q] + w[of * 20 + q * 2]
                                 : w[of * 20 + (q - 10) * 2 + 1];
        float s, c; __sincosf(0.5f * t, &s, &c);
        const int base = (q < 10) ? q : (10 + q);
        angs[wib][0][base] = c; angs[wib][0][base + 10] = s;
    }
    if (lane >= 12) {
        const int q = lane - 12, of = 2 * ofh + 1;
        const float t = (q < 10) ? x[nb * 10 + q] + w[of * 20 + q * 2]
                                 : w[of * 20 + (q - 10) * 2 + 1];
        float s, c; __sincosf(0.5f * t, &s, &c);
        const int base = (q < 10) ? q : (10 + q);
        angs[wib][1][base] = c; angs[wib][1][base + 10] = s;
    }
    __syncwarp();
    const float* const A0 = angs[wib][0];
    const float* const A1 = angs[wib][1];

    // --- Lane-bit suffix parities (shared by both circuits).
    const int p4  = (lane >> 4) & 1;
    const int p3  = p4 ^ ((lane >> 3) & 1);
    const int p2  = p3 ^ ((lane >> 2) & 1);
    const int p1  = p2 ^ ((lane >> 1) & 1);
    const int par = p1 ^ (lane & 1);

    // --- Front end (latency region), interleaved across circuits:
    //     product lane factor -> 4 conjugated shfl gates -> W1 -> W2.
    float lf[2];
#pragma unroll
    for (int c = 0; c < 2; c++) {
        const float* A = c ? A1 : A0;
        const float f0 = (lane & 1)        ? A[14] : A[4];
        const float f1 = ((lane >> 1) & 1) ? A[13] : A[3];
        const float f2 = ((lane >> 2) & 1) ? A[12] : A[2];
        const float f3 = ((lane >> 3) & 1) ? A[11] : A[1];
        const float f4 = ((lane >> 4) & 1) ? A[10] : A[0];
        lf[c] = (f0 * f1) * (f2 * f3) * f4;
    }
#pragma unroll
    for (int c = 0; c < 2; c++) {
        const float* A = c ? A1 : A0;
        float ss, p, v = lf[c];
        ss = p4 ? A[30] : -A[30];
        p = __shfl_xor_sync(FULL, v, 24); v = fmaf(A[20], v, ss * p);
        ss = p3 ? A[31] : -A[31];
        p = __shfl_xor_sync(FULL, v, 12); v = fmaf(A[21], v, ss * p);
        ss = p2 ? A[32] : -A[32];
        p = __shfl_xor_sync(FULL, v, 6);  v = fmaf(A[22], v, ss * p);
        ss = p1 ? A[33] : -A[33];
        p = __shfl_xor_sync(FULL, v, 3);  v = fmaf(A[23], v, ss * p);
        lf[c] = v;
    }

    float W2[2][4];
#pragma unroll
    for (int c = 0; c < 2; c++) {
        const float* A = c ? A1 : A0;
        const float Lp  = __shfl_xor_sync(FULL, lf[c], 1);
        const float sp4v = par ? A[34] : -A[34];
        // q=4 boundary: hoisted products (c24*c15, c24*s15, sp4*s15, sp4*c15).
        const float q4cc = A[24] * A[5],  q4cs = A[24] * A[15];
        const float q4ss = sp4v  * A[15], q4sc = sp4v  * A[5];
        const float W1_0 = fmaf(q4cc, lf[c], q4ss * Lp);
        const float W1_1 = fmaf(q4cs, lf[c], q4sc * Lp);
        // q=5: products (c25*c16, c25*s16, sp5*s16, sp5*c16).
        const float sp5v = par ? A[35] : -A[35];
        const float q5cc = A[25] * A[6],  q5cs = A[25] * A[16];
        const float q5ss = sp5v  * A[16], q5sc = sp5v  * A[6];
        W2[c][0] = fmaf(q5cc, W1_0,  q5ss * W1_1);
        W2[c][1] = fmaf(q5cs, W1_0,  q5sc * W1_1);
        W2[c][2] = fmaf(q5cc, W1_1, -q5ss * W1_0);
        W2[c][3] = fmaf(q5cs, W1_1, -q5sc * W1_0);
    }

    // --- Readout coefficient table (lane-only, shared by both circuits).
    const int E  = ((lane >> 1) ^ (lane >> 3)) & 1;
    const int O  = par ^ E;
    const int Ab = O + E + (((lane >> 2) ^ (lane >> 4)) & 1)
                 + ((lane >> 3) & 1) + ((lane >> 4) & 1);
    const float K  = (float)(10 - 2 * Ab - (E ? 6 : 0) - (O ? 4 : 0));
    const float ke = E ? 2.0f : -2.0f;
    const float ko = O ? 2.0f : -2.0f;
    float co[12];                         // co[ne*3 + no]
    co[0] = K;          co[3] = K + ke;     co[6] = co[3] + ke;  co[9]  = co[6] + ke;
    co[1] = co[0] + ko; co[4] = co[3] + ko; co[7] = co[6] + ko;  co[10] = co[9] + ko;
    co[2] = co[1] + ko; co[5] = co[4] + ko; co[8] = co[7] + ko;  co[11] = co[10] + ko;

    // --- Fused tail q=6..q=9 + readout, per circuit (sequential: small live set).
    float sum[2];
#pragma unroll
    for (int c = 0; c < 2; c++) {
        const float* A = c ? A1 : A0;
        // q=6 products (c26*c17, c26*s17, sp6*s17, sp6*c17).
        const float sp6v = par ? A[36] : -A[36];
        const float q6cc = A[26] * A[7],  q6cs = A[26] * A[17];
        const float q6ss = sp6v  * A[17], q6sc = sp6v  * A[7];
        // q=7 products (c27*c18, c27*s18, sp7*s18, sp7*c18).
        const float sp7v = par ? A[37] : -A[37];
        const float q7cc = A[27] * A[8],  q7cs = A[27] * A[18];
        const float q7ss = sp7v  * A[18], q7sc = sp7v  * A[8];
        // Fused q=8+q=9 constants (e = parity of W4 index).
        const float c9 = A[9], s9 = A[19], c29 = A[29], c28 = A[28];
        const float sp9v = par ? A[39] : -A[39];
        const float sp8v = par ? A[38] : -A[38];
        const float P = c29 * c9, Q = c29 * s9;
        const float R = sp9v * s9, Sg = sp9v * c9;
        const float Up = P + R, Um = P - R, Vp = Q + Sg, Vm = Q - Sg;
        float Ae[2], Be[2], Ce[2], De[2];
        Ae[0] = c28 * Up;  Be[0] = sp8v * Vp;   Ce[0] = c28 * Vm;  De[0] = sp8v * Um;
        Ae[1] = c28 * Um;  Be[1] = -sp8v * Vm;  Ce[1] = c28 * Vp;  De[1] = -sp8v * Up;

        float s0 = 0.0f, s1 = 0.0f;
#pragma unroll
        for (int g = 0; g < 4; g++) {
            const int e0 = PARf(g), e1 = e0 ^ 1;    // compile-time
            const float u0 = W2[c][g], u1 = W2[c][g ^ 1];
            // q=6: W3 pair for this group.
            const float w30 = fmaf(q6cc, u0, (e0 ? -q6ss : q6ss) * u1);
            const float w31 = fmaf(q6cs, u0, (e0 ? -q6sc : q6sc) * u1);
            // q=7: W4 quad. PARf(2g)=e0, PARf(2g+1)=e1.
            const float w40 = fmaf(q7cc, w30, (e0 ? -q7ss : q7ss) * w31);
            const float w41 = fmaf(q7cs, w30, (e0 ? -q7sc : q7sc) * w31);
            const float w42 = fmaf(q7cc, w31, (e0 ? q7ss : -q7ss) * w30);
            const float w43 = fmaf(q7cs, w31, (e0 ? q7sc : -q7sc) * w30);
            // q=8+q=9 fused: amps j = 8g..8g+7; W4 pairs (m, m^1).
            const float a0 = fmaf(Ae[e0], w40, Be[e0] * w41);   // m=4g
            const float a1 = fmaf(Ce[e0], w40, De[e0] * w41);
            const float a2 = fmaf(Ae[e1], w41, Be[e1] * w40);   // m=4g+1
            const float a3 = fmaf(Ce[e1], w41, De[e1] * w40);
            const float a4 = fmaf(Ae[e1], w42, Be[e1] * w43);   // m=4g+2
            const float a5 = fmaf(Ce[e1], w42, De[e1] * w43);
            const float a6 = fmaf(Ae[e0], w43, Be[e0] * w42);   // m=4g+3
            const float a7 = fmaf(Ce[e0], w43, De[e0] * w42);
            // Square-accumulate with compile-time coeff table indices.
            s0 = fmaf(a0 * a0, co[NEf(8*g+0)*3 + NOf(8*g+0)], s0);
            s1 = fmaf(a1 * a1, co[NEf(8*g+1)*3 + NOf(8*g+1)], s1);
            s0 = fmaf(a2 * a2, co[NEf(8*g+2)*3 + NOf(8*g+2)], s0);
            s1 = fmaf(a3 * a3, co[NEf(8*g+3)*3 + NOf(8*g+3)], s1);
            s0 = fmaf(a4 * a4, co[NEf(8*g+4)*3 + NOf(8*g+4)], s0);
            s1 = fmaf(a5 * a5, co[NEf(8*g+5)*3 + NOf(8*g+5)], s1);
            s0 = fmaf(a6 * a6, co[NEf(8*g+6)*3 + NOf(8*g+6)], s0);
            s1 = fmaf(a7 * a7, co[NEf(8*g+7)*3 + NOf(8*g+7)], s1);
        }
        sum[c] = s0 + s1;
    }

    // --- Warp reductions, interleaved.
#pragma unroll
    for (int off = 16; off; off >>= 1) {
        sum[0] += __shfl_xor_sync(FULL, sum[0], off);
        sum[1] += __shfl_xor_sync(FULL, sum[1], off);
    }

    if (lane == 0) {
        out[(2 * ofh)     * 128 + nb] = sum[0];
        out[(2 * ofh + 1) * 128 + nb] = sum[1];
    }
}

extern "C" void kernel_launch(void* const* d_in, const int* in_sizes, int n_in,
                              void* d_out, int out_size)
{
    const float* x = (const float*)d_in[0];   // (128, 10) fp32
    const float* w = (const float*)d_in[1];   // (64, 10, 2) fp32
    float* out = (float*)d_out;               // 8192 fp32

    // 4096 warps (2 circuits each), 4 warps/block -> 1024 blocks.
    qnn_kernel<<<1024, 128>>>(x, w, out);
}